// round 5
// baseline (speedup 1.0000x reference)
#include <cuda_runtime.h>
#include <cuda_bf16.h>
#include <math_constants.h>
#include <cstdint>

#define N_NODES 50000
#define HID     128
#define E_EDGES 640000
#define ATT_SLOPE 0.2f
#define OUT_SLOPE 0.01f

// ---------------- scratch (device globals; no allocation allowed) ----------
__device__ float g_xl[N_NODES * HID];
__device__ float g_xr[N_NODES * HID];
__device__ float g_h1[N_NODES * HID];
__device__ int   g_deg[N_NODES];
__device__ int   g_rowptr[N_NODES + 1];
__device__ int   g_cursor[N_NODES];
__device__ int   g_esrc[E_EDGES];

__device__ __forceinline__ float lrelu(float x, float s) { return x > 0.f ? x : s * x; }

__device__ __forceinline__ uint32_t s2u(const void* p) {
    uint32_t a;
    asm("{ .reg .u64 t; cvta.to.shared.u64 t, %1; cvt.u32.u64 %0, t; }" : "=r"(a) : "l"(p));
    return a;
}

// ---------------- CSR build ----------------
__global__ void k_zero_deg() {
    int i = blockIdx.x * blockDim.x + threadIdx.x;
    if (i < N_NODES) g_deg[i] = 0;
}
// 4 edges per thread -> 4 outstanding atomics (MLP)
__global__ void k_hist(const int* __restrict__ dst) {
    int i = (blockIdx.x * blockDim.x + threadIdx.x) * 4;
    if (i >= E_EDGES) return;
    int4 d = *(const int4*)(dst + i);
    atomicAdd(&g_deg[d.x], 1);
    atomicAdd(&g_deg[d.y], 1);
    atomicAdd(&g_deg[d.z], 1);
    atomicAdd(&g_deg[d.w], 1);
}
__global__ void __launch_bounds__(1024) k_scan() {
    __shared__ int ssum[1024];
    const int t = threadIdx.x;
    const int CH = (N_NODES + 1023) / 1024;
    const int base = t * CH;
    int s = 0;
    for (int j = 0; j < CH; j++) { int idx = base + j; if (idx < N_NODES) s += g_deg[idx]; }
    ssum[t] = s;
    __syncthreads();
    for (int off = 1; off < 1024; off <<= 1) {
        int v = (t >= off) ? ssum[t - off] : 0;
        __syncthreads();
        ssum[t] += v;
        __syncthreads();
    }
    int run = (t == 0) ? 0 : ssum[t - 1];
    for (int j = 0; j < CH; j++) {
        int idx = base + j;
        if (idx < N_NODES) { g_rowptr[idx] = run; g_cursor[idx] = run; run += g_deg[idx]; }
    }
    if (t == 1023) g_rowptr[N_NODES] = ssum[1023];
}
__global__ void k_scatter(const int* __restrict__ src, const int* __restrict__ dst) {
    int i = (blockIdx.x * blockDim.x + threadIdx.x) * 4;
    if (i >= E_EDGES) return;
    int4 d = *(const int4*)(dst + i);
    int4 s = *(const int4*)(src + i);
    int p0 = atomicAdd(&g_cursor[d.x], 1);
    int p1 = atomicAdd(&g_cursor[d.y], 1);
    int p2 = atomicAdd(&g_cursor[d.z], 1);
    int p3 = atomicAdd(&g_cursor[d.w], 1);
    g_esrc[p0] = s.x;
    g_esrc[p1] = s.y;
    g_esrc[p2] = s.z;
    g_esrc[p3] = s.w;
}

// ---------------- split-bf16 HMMA GEMM (unchanged from R4) ------------------
#define LDP   136
#define LDPU  68
#define SMEM_AHI 0
#define SMEM_ALO (SMEM_AHI + 128 * LDP * 2)
#define SMEM_BHI (SMEM_ALO + 128 * LDP * 2)
#define SMEM_BLO (SMEM_BHI + 256 * LDP * 2)
#define SMEM_TOT (SMEM_BLO + 256 * LDP * 2)

__device__ __forceinline__ void ldsm4(uint32_t& r0, uint32_t& r1, uint32_t& r2,
                                      uint32_t& r3, uint32_t addr) {
    asm volatile("ldmatrix.sync.aligned.m8n8.x4.shared.b16 {%0,%1,%2,%3}, [%4];"
                 : "=r"(r0), "=r"(r1), "=r"(r2), "=r"(r3) : "r"(addr));
}
__device__ __forceinline__ void mma16816(float* c, const uint32_t* a, const uint32_t* b) {
    asm volatile(
        "mma.sync.aligned.m16n8k16.row.col.f32.bf16.bf16.f32 "
        "{%0,%1,%2,%3}, {%4,%5,%6,%7}, {%8,%9}, {%0,%1,%2,%3};"
        : "+f"(c[0]), "+f"(c[1]), "+f"(c[2]), "+f"(c[3])
        : "r"(a[0]), "r"(a[1]), "r"(a[2]), "r"(a[3]), "r"(b[0]), "r"(b[1]));
}
__device__ __forceinline__ uint32_t pack_hi(float x, float y) {
    __nv_bfloat16 hx = __float2bfloat16(x), hy = __float2bfloat16(y);
    return ((uint32_t)__bfloat16_as_ushort(hy) << 16) | __bfloat16_as_ushort(hx);
}
__device__ __forceinline__ uint32_t pack_lo(float x, float y) {
    __nv_bfloat16 hx = __float2bfloat16(x), hy = __float2bfloat16(y);
    __nv_bfloat16 lx = __float2bfloat16(x - __bfloat162float(hx));
    __nv_bfloat16 ly = __float2bfloat16(y - __bfloat162float(hy));
    return ((uint32_t)__bfloat16_as_ushort(ly) << 16) | __bfloat16_as_ushort(lx);
}

__global__ void __launch_bounds__(512, 1)
k_gemm_tc(const float* __restrict__ X,
          const float* __restrict__ wl, const float* __restrict__ wr) {
    extern __shared__ char smem[];
    const uint32_t sb = s2u(smem);
    const int tid  = threadIdx.x;
    const int warp = tid >> 5;
    const int lane = tid & 31;
    uint32_t* su = (uint32_t*)smem;

    for (int i = tid; i < 256 * 64; i += 512) {
        int n = i >> 6, p = i & 63;
        const float* wp = ((n < 128) ? wl : wr) + (size_t)(n & 127) * 128 + p * 2;
        float2 v = *(const float2*)wp;
        su[(SMEM_BHI >> 2) + n * LDPU + p] = pack_hi(v.x, v.y);
        su[(SMEM_BLO >> 2) + n * LDPU + p] = pack_lo(v.x, v.y);
    }
    for (int i = tid; i < 128 * 64; i += 512) {
        int r = i >> 6, p = i & 63;
        long grow = (long)blockIdx.x * 128 + r;
        float2 v = make_float2(0.f, 0.f);
        if (grow < N_NODES) v = *(const float2*)(X + grow * HID + p * 2);
        su[(SMEM_AHI >> 2) + r * LDPU + p] = pack_hi(v.x, v.y);
        su[(SMEM_ALO >> 2) + r * LDPU + p] = pack_lo(v.x, v.y);
    }
    __syncthreads();

    const int wm = (warp >> 2) * 32;
    const int wn = (warp & 3) * 64;
    float c[2][8][4];
#pragma unroll
    for (int mi = 0; mi < 2; mi++)
#pragma unroll
        for (int ni = 0; ni < 8; ni++)
#pragma unroll
            for (int q = 0; q < 4; q++) c[mi][ni][q] = 0.f;

    const uint32_t aRowOff = (uint32_t)((wm + (lane & 15)) * LDP + ((lane >> 4) << 3)) << 1;
    const uint32_t bRowOff = (uint32_t)((wn + ((lane >> 4) << 3) + (lane & 7)) * LDP
                                        + (((lane >> 3) & 1) << 3)) << 1;

#pragma unroll
    for (int term = 0; term < 3; term++) {
        const uint32_t Ab = sb + (term == 2 ? SMEM_ALO : SMEM_AHI) + aRowOff;
        const uint32_t Bb = sb + (term == 1 ? SMEM_BLO : SMEM_BHI) + bRowOff;
#pragma unroll
        for (int k0 = 0; k0 < 128; k0 += 16) {
            uint32_t a[2][4];
            ldsm4(a[0][0], a[0][1], a[0][2], a[0][3], Ab + (k0 << 1));
            ldsm4(a[1][0], a[1][1], a[1][2], a[1][3], Ab + ((16 * LDP) << 1) + (k0 << 1));
            uint32_t b[8][2];
#pragma unroll
            for (int nq = 0; nq < 4; nq++) {
                uint32_t r0, r1, r2, r3;
                ldsm4(r0, r1, r2, r3, Bb + ((nq * 16 * LDP) << 1) + (k0 << 1));
                b[nq * 2][0] = r0; b[nq * 2][1] = r1;
                b[nq * 2 + 1][0] = r2; b[nq * 2 + 1][1] = r3;
            }
#pragma unroll
            for (int mi = 0; mi < 2; mi++)
#pragma unroll
                for (int ni = 0; ni < 8; ni++)
                    mma16816(c[mi][ni], a[mi], b[ni]);
        }
    }

    float* buf = (wn < 128) ? g_xl : g_xr;
    const int colbase = (wn & 127) + (lane & 3) * 2;
#pragma unroll
    for (int mi = 0; mi < 2; mi++) {
#pragma unroll
        for (int half = 0; half < 2; half++) {
            long row = (long)blockIdx.x * 128 + wm + mi * 16 + (lane >> 2) + half * 8;
            if (row >= N_NODES) continue;
            float* rp = buf + row * HID + colbase;
#pragma unroll
            for (int ni = 0; ni < 8; ni++) {
                float2 v = make_float2(c[mi][ni][half * 2], c[mi][ni][half * 2 + 1]);
                *(float2*)(rp + ni * 8) = v;
            }
        }
    }
}

// ---------------- fused per-node attention (unrolled x4 for MLP) -----------
template <int LAYER>
__global__ void k_node(const float* __restrict__ att, const float* __restrict__ b,
                       float* __restrict__ outbuf) {
    const int n    = (blockIdx.x * blockDim.x + threadIdx.x) >> 5;
    const int lane = threadIdx.x & 31;
    if (n >= N_NODES) return;

    const int beg = g_rowptr[n];
    const int end = g_rowptr[n + 1];

    const float4 xr = *(const float4*)(g_xr + (size_t)n * HID + lane * 4);
    const float4 at = *(const float4*)(att + lane * 4);

    float4 acc = make_float4(0.f, 0.f, 0.f, 0.f);
    float  sum = 0.f;

    for (int i0 = beg; i0 < end; i0 += 32) {
        const int cnt = min(32, end - i0);
        int sid = (lane < cnt) ? g_esrc[i0 + lane] : 0;
        int j = 0;
        for (; j + 4 <= cnt; j += 4) {
            const int s0 = __shfl_sync(0xffffffffu, sid, j);
            const int s1 = __shfl_sync(0xffffffffu, sid, j + 1);
            const int s2 = __shfl_sync(0xffffffffu, sid, j + 2);
            const int s3 = __shfl_sync(0xffffffffu, sid, j + 3);
            const float4 x0 = *(const float4*)(g_xl + (size_t)s0 * HID + lane * 4);
            const float4 x1 = *(const float4*)(g_xl + (size_t)s1 * HID + lane * 4);
            const float4 x2 = *(const float4*)(g_xl + (size_t)s2 * HID + lane * 4);
            const float4 x3 = *(const float4*)(g_xl + (size_t)s3 * HID + lane * 4);
            float p0 = lrelu(x0.x + xr.x, ATT_SLOPE) * at.x
                     + lrelu(x0.y + xr.y, ATT_SLOPE) * at.y
                     + lrelu(x0.z + xr.z, ATT_SLOPE) * at.z
                     + lrelu(x0.w + xr.w, ATT_SLOPE) * at.w;
            float p1 = lrelu(x1.x + xr.x, ATT_SLOPE) * at.x
                     + lrelu(x1.y + xr.y, ATT_SLOPE) * at.y
                     + lrelu(x1.z + xr.z, ATT_SLOPE) * at.z
                     + lrelu(x1.w + xr.w, ATT_SLOPE) * at.w;
            float p2 = lrelu(x2.x + xr.x, ATT_SLOPE) * at.x
                     + lrelu(x2.y + xr.y, ATT_SLOPE) * at.y
                     + lrelu(x2.z + xr.z, ATT_SLOPE) * at.z
                     + lrelu(x2.w + xr.w, ATT_SLOPE) * at.w;
            float p3 = lrelu(x3.x + xr.x, ATT_SLOPE) * at.x
                     + lrelu(x3.y + xr.y, ATT_SLOPE) * at.y
                     + lrelu(x3.z + xr.z, ATT_SLOPE) * at.z
                     + lrelu(x3.w + xr.w, ATT_SLOPE) * at.w;
#pragma unroll
            for (int m = 8; m >= 1; m >>= 1) {
                p0 += __shfl_xor_sync(0xffffffffu, p0, m);
                p1 += __shfl_xor_sync(0xffffffffu, p1, m);
                p2 += __shfl_xor_sync(0xffffffffu, p2, m);
                p3 += __shfl_xor_sync(0xffffffffu, p3, m);
            }
            const float e0 = __expf(p0), e1 = __expf(p1);
            const float e2 = __expf(p2), e3 = __expf(p3);
            sum += (e0 + e1) + (e2 + e3);
            acc.x = fmaf(e0, x0.x, fmaf(e1, x1.x, fmaf(e2, x2.x, fmaf(e3, x3.x, acc.x))));
            acc.y = fmaf(e0, x0.y, fmaf(e1, x1.y, fmaf(e2, x2.y, fmaf(e3, x3.y, acc.y))));
            acc.z = fmaf(e0, x0.z, fmaf(e1, x1.z, fmaf(e2, x2.z, fmaf(e3, x3.z, acc.z))));
            acc.w = fmaf(e0, x0.w, fmaf(e1, x1.w, fmaf(e2, x2.w, fmaf(e3, x3.w, acc.w))));
        }
        for (; j < cnt; j++) {
            const int s = __shfl_sync(0xffffffffu, sid, j);
            const float4 xl = *(const float4*)(g_xl + (size_t)s * HID + lane * 4);
            float p = lrelu(xl.x + xr.x, ATT_SLOPE) * at.x
                    + lrelu(xl.y + xr.y, ATT_SLOPE) * at.y
                    + lrelu(xl.z + xr.z, ATT_SLOPE) * at.z
                    + lrelu(xl.w + xr.w, ATT_SLOPE) * at.w;
#pragma unroll
            for (int m = 8; m >= 1; m >>= 1)
                p += __shfl_xor_sync(0xffffffffu, p, m);
            const float ex = __expf(p);
            sum += ex;
            acc.x = fmaf(ex, xl.x, acc.x);
            acc.y = fmaf(ex, xl.y, acc.y);
            acc.z = fmaf(ex, xl.z, acc.z);
            acc.w = fmaf(ex, xl.w, acc.w);
        }
    }

    const float inv = 1.f / (sum + 1e-16f);
    const float4 bb = *(const float4*)(b + lane * 4);
    float4 o;
    o.x = fmaf(acc.x, inv, bb.x);
    o.y = fmaf(acc.y, inv, bb.y);
    o.z = fmaf(acc.z, inv, bb.z);
    o.w = fmaf(acc.w, inv, bb.w);

    float* dstp = outbuf + (size_t)n * HID + lane * 4;
    if (LAYER == 1) {
        o.x = lrelu(o.x, OUT_SLOPE);
        o.y = lrelu(o.y, OUT_SLOPE);
        o.z = lrelu(o.z, OUT_SLOPE);
        o.w = lrelu(o.w, OUT_SLOPE);
        *(float4*)dstp = o;
    } else {
        const float4 h = *(const float4*)(g_h1 + (size_t)n * HID + lane * 4);
        o.x += h.x; o.y += h.y; o.z += h.z; o.w += h.w;
        *(float4*)dstp = o;
    }
}

// ---------------- launch ----------------
extern "C" void kernel_launch(void* const* d_in, const int* in_sizes, int n_in,
                              void* d_out, int out_size) {
    const float* x    = (const float*)d_in[0];
    const int*   ei   = (const int*)d_in[1];
    const float* wl1  = (const float*)d_in[2];
    const float* wr1  = (const float*)d_in[3];
    const float* att1 = (const float*)d_in[4];
    const float* b1   = (const float*)d_in[5];
    const float* wl2  = (const float*)d_in[6];
    const float* wr2  = (const float*)d_in[7];
    const float* att2 = (const float*)d_in[8];
    const float* b2   = (const float*)d_in[9];
    float* out = (float*)d_out;

    const int* src = ei;
    const int* dst = ei + E_EDGES;

    void* h1_ptr = nullptr;
    cudaGetSymbolAddress(&h1_ptr, g_h1);

    cudaFuncSetAttribute(k_gemm_tc, cudaFuncAttributeMaxDynamicSharedMemorySize, SMEM_TOT);

    const int gemm_blocks = (N_NODES + 127) / 128;          // 391
    const int node_blocks = (N_NODES * 32 + 255) / 256;     // 6250
    const int e4_blocks   = (E_EDGES / 4 + 255) / 256;      // 625
    const int n_blocks    = (N_NODES + 255) / 256;

    // CSR pieces interleaved so k_gemm_tc lands in profiler capture slot #4.
    k_zero_deg<<<n_blocks, 256>>>();
    k_hist<<<e4_blocks, 256>>>(dst);
    k_scan<<<1, 1024>>>();
    k_gemm_tc<<<gemm_blocks, 512, SMEM_TOT>>>(x, wl1, wr1);     // layer-1 GEMM (CSR-independent)
    k_scatter<<<e4_blocks, 256>>>(src, dst);
    k_node<1><<<node_blocks, 256>>>(att1, b1, (float*)h1_ptr);

    k_gemm_tc<<<gemm_blocks, 512, SMEM_TOT>>>((const float*)h1_ptr, wl2, wr2);
    k_node<2><<<node_blocks, 256>>>(att2, b2, out);
}

// round 6
// speedup vs baseline: 1.2040x; 1.2040x over previous
#include <cuda_runtime.h>
#include <cuda_bf16.h>
#include <math_constants.h>
#include <cstdint>

#define N_NODES 50000
#define HID     128
#define E_EDGES 640000
#define ATT_SLOPE 0.2f
#define OUT_SLOPE 0.01f

// ---------------- scratch (device globals; no allocation allowed) ----------
__device__ float g_xl[N_NODES * HID];
__device__ float g_xr[N_NODES * HID];
__device__ float g_h1[N_NODES * HID];
__device__ int   g_deg[N_NODES];
__device__ int   g_rowptr[N_NODES + 1];
__device__ int   g_cursor[N_NODES];
__device__ int   g_esrc[E_EDGES];
// W bf16 hi/lo images per layer: [n=256][k=128] bf16 packed as u32 pairs
__device__ uint32_t g_w1hi[256 * 64];
__device__ uint32_t g_w1lo[256 * 64];
__device__ uint32_t g_w2hi[256 * 64];
__device__ uint32_t g_w2lo[256 * 64];

__device__ __forceinline__ float lrelu(float x, float s) { return x > 0.f ? x : s * x; }

__device__ __forceinline__ uint32_t s2u(const void* p) {
    uint32_t a;
    asm("{ .reg .u64 t; cvta.to.shared.u64 t, %1; cvt.u32.u64 %0, t; }" : "=r"(a) : "l"(p));
    return a;
}
__device__ __forceinline__ void cpasync16(uint32_t dst, const void* src) {
    asm volatile("cp.async.cg.shared.global [%0], [%1], 16;" :: "r"(dst), "l"(src));
}

// ---------------- CSR build (R4 versions — known 369us baseline) -----------
__global__ void k_zero_deg() {
    int i = blockIdx.x * blockDim.x + threadIdx.x;
    if (i < N_NODES) g_deg[i] = 0;
}
__global__ void k_hist(const int* __restrict__ dst) {
    int i = blockIdx.x * blockDim.x + threadIdx.x;
    if (i < E_EDGES) atomicAdd(&g_deg[dst[i]], 1);
}
__global__ void __launch_bounds__(1024) k_scan() {
    __shared__ int ssum[1024];
    const int t = threadIdx.x;
    const int CH = (N_NODES + 1023) / 1024;
    const int base = t * CH;
    int s = 0;
    for (int j = 0; j < CH; j++) { int idx = base + j; if (idx < N_NODES) s += g_deg[idx]; }
    ssum[t] = s;
    __syncthreads();
    for (int off = 1; off < 1024; off <<= 1) {
        int v = (t >= off) ? ssum[t - off] : 0;
        __syncthreads();
        ssum[t] += v;
        __syncthreads();
    }
    int run = (t == 0) ? 0 : ssum[t - 1];
    for (int j = 0; j < CH; j++) {
        int idx = base + j;
        if (idx < N_NODES) { g_rowptr[idx] = run; g_cursor[idx] = run; run += g_deg[idx]; }
    }
    if (t == 1023) g_rowptr[N_NODES] = ssum[1023];
}
__global__ void k_scatter(const int* __restrict__ src, const int* __restrict__ dst) {
    int i = blockIdx.x * blockDim.x + threadIdx.x;
    if (i < E_EDGES) {
        int p = atomicAdd(&g_cursor[dst[i]], 1);
        g_esrc[p] = src[i];
    }
}

// ---------------- bf16 split helpers ----------------------------------------
__device__ __forceinline__ uint32_t pack_hi(float x, float y) {
    __nv_bfloat16 hx = __float2bfloat16(x), hy = __float2bfloat16(y);
    return ((uint32_t)__bfloat16_as_ushort(hy) << 16) | __bfloat16_as_ushort(hx);
}
__device__ __forceinline__ uint32_t pack_lo(float x, float y) {
    __nv_bfloat16 hx = __float2bfloat16(x), hy = __float2bfloat16(y);
    __nv_bfloat16 lx = __float2bfloat16(x - __bfloat162float(hx));
    __nv_bfloat16 ly = __float2bfloat16(y - __bfloat162float(hy));
    return ((uint32_t)__bfloat16_as_ushort(ly) << 16) | __bfloat16_as_ushort(lx);
}

// W image prep: [n=256][k=128] fp32 -> bf16 hi/lo, once per layer
__global__ void k_prepw(const float* __restrict__ wl, const float* __restrict__ wr,
                        uint32_t* __restrict__ hi, uint32_t* __restrict__ lo) {
    int i = blockIdx.x * blockDim.x + threadIdx.x;
    if (i >= 256 * 64) return;
    int n = i >> 6, p = i & 63;
    const float* wp = ((n < 128) ? wl : wr) + (size_t)(n & 127) * 128 + p * 2;
    float2 v = *(const float2*)wp;
    hi[i] = pack_hi(v.x, v.y);
    lo[i] = pack_lo(v.x, v.y);
}

// ---------------- split-bf16 HMMA GEMM v3 ------------------------------------
// Tile: M=128 x N=64, 256 threads (8 warps, 4M x 2N), warp tile 32x32.
// SMEM 104.4 KB -> 2 CTAs/SM. B staged via cp.async from prebuilt bf16 images
// (overlaps the A fp32->bf16 conversion). D = Xhi*Whi + Xhi*Wlo + Xlo*Whi.
#define LDP   136
#define LDPU  68
#define SMEM_AHI 0
#define SMEM_ALO (SMEM_AHI + 128 * LDP * 2)      //  34816
#define SMEM_BHI (SMEM_ALO + 128 * LDP * 2)      //  69632
#define SMEM_BLO (SMEM_BHI + 64 * LDP * 2)       //  87040
#define SMEM_TOT (SMEM_BLO + 64 * LDP * 2)       // 104448

__device__ __forceinline__ void ldsm4(uint32_t& r0, uint32_t& r1, uint32_t& r2,
                                      uint32_t& r3, uint32_t addr) {
    asm volatile("ldmatrix.sync.aligned.m8n8.x4.shared.b16 {%0,%1,%2,%3}, [%4];"
                 : "=r"(r0), "=r"(r1), "=r"(r2), "=r"(r3) : "r"(addr));
}
__device__ __forceinline__ void mma16816(float* c, const uint32_t* a, const uint32_t* b) {
    asm volatile(
        "mma.sync.aligned.m16n8k16.row.col.f32.bf16.bf16.f32 "
        "{%0,%1,%2,%3}, {%4,%5,%6,%7}, {%8,%9}, {%0,%1,%2,%3};"
        : "+f"(c[0]), "+f"(c[1]), "+f"(c[2]), "+f"(c[3])
        : "r"(a[0]), "r"(a[1]), "r"(a[2]), "r"(a[3]), "r"(b[0]), "r"(b[1]));
}

__global__ void __launch_bounds__(256, 2)
k_gemm_tc(const float* __restrict__ X,
          const uint32_t* __restrict__ whi, const uint32_t* __restrict__ wlo) {
    extern __shared__ char smem[];
    const uint32_t sb = s2u(smem);
    const int tid  = threadIdx.x;
    const int warp = tid >> 5;
    const int lane = tid & 31;
    const int mblk = blockIdx.x >> 2;
    const int nblk = blockIdx.x & 3;
    uint32_t* su = (uint32_t*)smem;

    // ---- B stage via cp.async: 64 rows x 256B per image, 16B chunks ----
    {
        const char* bh = (const char*)(whi + (size_t)nblk * 64 * 64);
        const char* bl = (const char*)(wlo + (size_t)nblk * 64 * 64);
        for (int c = tid; c < 1024; c += 256) {
            int row = c >> 4, seg = c & 15;
            uint32_t doff = (uint32_t)(row * (LDP * 2) + seg * 16);
            uint32_t soff = (uint32_t)(row * 256 + seg * 16);
            cpasync16(sb + SMEM_BHI + doff, bh + soff);
            cpasync16(sb + SMEM_BLO + doff, bl + soff);
        }
        asm volatile("cp.async.commit_group;" ::: "memory");
    }

    // ---- A stage: 128 rows fp32 -> bf16 hi/lo (overlaps cp.async) ----
    for (int i = tid; i < 128 * 64; i += 256) {
        int r = i >> 6, p = i & 63;
        long grow = (long)mblk * 128 + r;
        float2 v = make_float2(0.f, 0.f);
        if (grow < N_NODES) v = *(const float2*)(X + grow * HID + p * 2);
        su[(SMEM_AHI >> 2) + r * LDPU + p] = pack_hi(v.x, v.y);
        su[(SMEM_ALO >> 2) + r * LDPU + p] = pack_lo(v.x, v.y);
    }
    asm volatile("cp.async.wait_group 0;" ::: "memory");
    __syncthreads();

    // ---- compute: 8 warps as 4M x 2N, warp tile 32x32 ----
    const int wm = (warp >> 1) * 32;
    const int wn = (warp & 1) * 32;
    float c[2][4][4];
#pragma unroll
    for (int mi = 0; mi < 2; mi++)
#pragma unroll
        for (int ni = 0; ni < 4; ni++)
#pragma unroll
            for (int q = 0; q < 4; q++) c[mi][ni][q] = 0.f;

    const uint32_t aRowOff = (uint32_t)((wm + (lane & 15)) * LDP + ((lane >> 4) << 3)) << 1;
    const uint32_t bRowOff = (uint32_t)((wn + ((lane >> 4) << 3) + (lane & 7)) * LDP
                                        + (((lane >> 3) & 1) << 3)) << 1;

#pragma unroll
    for (int term = 0; term < 3; term++) {
        const uint32_t Ab = sb + (term == 2 ? SMEM_ALO : SMEM_AHI) + aRowOff;
        const uint32_t Bb = sb + (term == 1 ? SMEM_BLO : SMEM_BHI) + bRowOff;
#pragma unroll
        for (int k0 = 0; k0 < 128; k0 += 16) {
            uint32_t a[2][4];
            ldsm4(a[0][0], a[0][1], a[0][2], a[0][3], Ab + (k0 << 1));
            ldsm4(a[1][0], a[1][1], a[1][2], a[1][3], Ab + ((16 * LDP) << 1) + (k0 << 1));
            uint32_t b[4][2];
#pragma unroll
            for (int nq = 0; nq < 2; nq++) {
                uint32_t r0, r1, r2, r3;
                ldsm4(r0, r1, r2, r3, Bb + ((nq * 16 * LDP) << 1) + (k0 << 1));
                b[nq * 2][0] = r0; b[nq * 2][1] = r1;
                b[nq * 2 + 1][0] = r2; b[nq * 2 + 1][1] = r3;
            }
#pragma unroll
            for (int mi = 0; mi < 2; mi++)
#pragma unroll
                for (int ni = 0; ni < 4; ni++)
                    mma16816(c[mi][ni], a[mi], b[ni]);
        }
    }

    // ---- epilogue: logical cols [nblk*64 + wn, +32) ----
    float* buf = (nblk < 2) ? g_xl : g_xr;
    const int colbase = ((nblk * 64) & 127) + wn + (lane & 3) * 2;
#pragma unroll
    for (int mi = 0; mi < 2; mi++) {
#pragma unroll
        for (int half = 0; half < 2; half++) {
            long row = (long)mblk * 128 + wm + mi * 16 + (lane >> 2) + half * 8;
            if (row >= N_NODES) continue;
            float* rp = buf + row * HID + colbase;
#pragma unroll
            for (int ni = 0; ni < 4; ni++) {
                float2 v = make_float2(c[mi][ni][half * 2], c[mi][ni][half * 2 + 1]);
                *(float2*)(rp + ni * 8) = v;
            }
        }
    }
}

// ---------------- fused per-node attention (R4 version) --------------------
template <int LAYER>
__global__ void k_node(const float* __restrict__ att, const float* __restrict__ b,
                       float* __restrict__ outbuf) {
    const int n    = (blockIdx.x * blockDim.x + threadIdx.x) >> 5;
    const int lane = threadIdx.x & 31;
    if (n >= N_NODES) return;

    const int beg = g_rowptr[n];
    const int end = g_rowptr[n + 1];

    const float4 xr = *(const float4*)(g_xr + (size_t)n * HID + lane * 4);
    const float4 at = *(const float4*)(att + lane * 4);

    float4 acc = make_float4(0.f, 0.f, 0.f, 0.f);
    float  sum = 0.f;

    for (int i0 = beg; i0 < end; i0 += 32) {
        const int cnt = min(32, end - i0);
        int sid = (lane < cnt) ? g_esrc[i0 + lane] : 0;
        for (int j = 0; j < cnt; j++) {
            const int s = __shfl_sync(0xffffffffu, sid, j);
            const float4 xl = *(const float4*)(g_xl + (size_t)s * HID + lane * 4);
            float p = lrelu(xl.x + xr.x, ATT_SLOPE) * at.x
                    + lrelu(xl.y + xr.y, ATT_SLOPE) * at.y
                    + lrelu(xl.z + xr.z, ATT_SLOPE) * at.z
                    + lrelu(xl.w + xr.w, ATT_SLOPE) * at.w;
            p += __shfl_xor_sync(0xffffffffu, p, 8);
            p += __shfl_xor_sync(0xffffffffu, p, 4);
            p += __shfl_xor_sync(0xffffffffu, p, 2);
            p += __shfl_xor_sync(0xffffffffu, p, 1);
            const float ex = __expf(p);
            sum += ex;
            acc.x = fmaf(ex, xl.x, acc.x);
            acc.y = fmaf(ex, xl.y, acc.y);
            acc.z = fmaf(ex, xl.z, acc.z);
            acc.w = fmaf(ex, xl.w, acc.w);
        }
    }

    const float inv = 1.f / (sum + 1e-16f);
    const float4 bb = *(const float4*)(b + lane * 4);
    float4 o;
    o.x = fmaf(acc.x, inv, bb.x);
    o.y = fmaf(acc.y, inv, bb.y);
    o.z = fmaf(acc.z, inv, bb.z);
    o.w = fmaf(acc.w, inv, bb.w);

    float* dstp = outbuf + (size_t)n * HID + lane * 4;
    if (LAYER == 1) {
        o.x = lrelu(o.x, OUT_SLOPE);
        o.y = lrelu(o.y, OUT_SLOPE);
        o.z = lrelu(o.z, OUT_SLOPE);
        o.w = lrelu(o.w, OUT_SLOPE);
        *(float4*)dstp = o;
    } else {
        const float4 h = *(const float4*)(g_h1 + (size_t)n * HID + lane * 4);
        o.x += h.x; o.y += h.y; o.z += h.z; o.w += h.w;
        *(float4*)dstp = o;
    }
}

// ---------------- launch ----------------
extern "C" void kernel_launch(void* const* d_in, const int* in_sizes, int n_in,
                              void* d_out, int out_size) {
    const float* x    = (const float*)d_in[0];
    const int*   ei   = (const int*)d_in[1];
    const float* wl1  = (const float*)d_in[2];
    const float* wr1  = (const float*)d_in[3];
    const float* att1 = (const float*)d_in[4];
    const float* b1   = (const float*)d_in[5];
    const float* wl2  = (const float*)d_in[6];
    const float* wr2  = (const float*)d_in[7];
    const float* att2 = (const float*)d_in[8];
    const float* b2   = (const float*)d_in[9];
    float* out = (float*)d_out;

    const int* src = ei;
    const int* dst = ei + E_EDGES;

    void* h1_ptr = nullptr;
    cudaGetSymbolAddress(&h1_ptr, g_h1);
    void *w1hi, *w1lo, *w2hi, *w2lo;
    cudaGetSymbolAddress(&w1hi, g_w1hi);
    cudaGetSymbolAddress(&w1lo, g_w1lo);
    cudaGetSymbolAddress(&w2hi, g_w2hi);
    cudaGetSymbolAddress(&w2lo, g_w2lo);

    cudaFuncSetAttribute(k_gemm_tc, cudaFuncAttributeMaxDynamicSharedMemorySize, SMEM_TOT);

    const int gemm_blocks = ((N_NODES + 127) / 128) * 4;    // 1564
    const int node_blocks = (N_NODES * 32 + 255) / 256;     // 6250
    const int e_blocks    = (E_EDGES + 255) / 256;
    const int n_blocks    = (N_NODES + 255) / 256;
    const int w_blocks    = (256 * 64 + 255) / 256;         // 64

    // slot-4 (profiled) = layer-1 GEMM
    k_prepw<<<w_blocks, 256>>>(wl1, wr1, (uint32_t*)w1hi, (uint32_t*)w1lo);
    k_prepw<<<w_blocks, 256>>>(wl2, wr2, (uint32_t*)w2hi, (uint32_t*)w2lo);
    k_zero_deg<<<n_blocks, 256>>>();
    k_gemm_tc<<<gemm_blocks, 256, SMEM_TOT>>>(x, (const uint32_t*)w1hi, (const uint32_t*)w1lo);
    k_hist<<<e_blocks, 256>>>(dst);
    k_scan<<<1, 1024>>>();
    k_scatter<<<e_blocks, 256>>>(src, dst);
    k_node<1><<<node_blocks, 256>>>(att1, b1, (float*)h1_ptr);

    k_gemm_tc<<<gemm_blocks, 256, SMEM_TOT>>>((const float*)h1_ptr,
                                              (const uint32_t*)w2hi, (const uint32_t*)w2lo);
    k_node<2><<<node_blocks, 256>>>(att2, b2, out);
}

// round 7
// speedup vs baseline: 1.3145x; 1.0918x over previous
#include <cuda_runtime.h>
#include <cuda_bf16.h>
#include <math_constants.h>
#include <cstdint>

#define N_NODES 50000
#define HID     128
#define E_EDGES 640000
#define ATT_SLOPE 0.2f
#define OUT_SLOPE 0.01f

// ---------------- scratch (device globals; no allocation allowed) ----------
__device__ float g_xl[N_NODES * HID];
__device__ float g_xr[N_NODES * HID];
__device__ float g_h1[N_NODES * HID];
__device__ int   g_deg[N_NODES];
__device__ int   g_rowptr[N_NODES + 1];
__device__ int   g_cursor[N_NODES];
__device__ int   g_esrc[E_EDGES];
// bf16 hi/lo images: X rows [row][64 u32], W [n=256][64 u32]
__device__ uint32_t g_xhi[N_NODES * 64];
__device__ uint32_t g_xlo[N_NODES * 64];
__device__ uint32_t g_w1hi[256 * 64];
__device__ uint32_t g_w1lo[256 * 64];
__device__ uint32_t g_w2hi[256 * 64];
__device__ uint32_t g_w2lo[256 * 64];

__device__ __forceinline__ float lrelu(float x, float s) { return x > 0.f ? x : s * x; }

__device__ __forceinline__ uint32_t s2u(const void* p) {
    uint32_t a;
    asm("{ .reg .u64 t; cvta.to.shared.u64 t, %1; cvt.u32.u64 %0, t; }" : "=r"(a) : "l"(p));
    return a;
}
__device__ __forceinline__ void cpasync16(uint32_t dst, const void* src) {
    asm volatile("cp.async.cg.shared.global [%0], [%1], 16;" :: "r"(dst), "l"(src));
}
__device__ __forceinline__ void cpasync16p(uint32_t dst, const void* src, int sz) {
    asm volatile("cp.async.cg.shared.global [%0], [%1], 16, %2;"
                 :: "r"(dst), "l"(src), "r"(sz));
}

// ---------------- CSR build (unchanged, 319us baseline) --------------------
__global__ void k_zero_deg() {
    int i = blockIdx.x * blockDim.x + threadIdx.x;
    if (i < N_NODES) g_deg[i] = 0;
}
__global__ void k_hist(const int* __restrict__ dst) {
    int i = blockIdx.x * blockDim.x + threadIdx.x;
    if (i < E_EDGES) atomicAdd(&g_deg[dst[i]], 1);
}
__global__ void __launch_bounds__(1024) k_scan() {
    __shared__ int ssum[1024];
    const int t = threadIdx.x;
    const int CH = (N_NODES + 1023) / 1024;
    const int base = t * CH;
    int s = 0;
    for (int j = 0; j < CH; j++) { int idx = base + j; if (idx < N_NODES) s += g_deg[idx]; }
    ssum[t] = s;
    __syncthreads();
    for (int off = 1; off < 1024; off <<= 1) {
        int v = (t >= off) ? ssum[t - off] : 0;
        __syncthreads();
        ssum[t] += v;
        __syncthreads();
    }
    int run = (t == 0) ? 0 : ssum[t - 1];
    for (int j = 0; j < CH; j++) {
        int idx = base + j;
        if (idx < N_NODES) { g_rowptr[idx] = run; g_cursor[idx] = run; run += g_deg[idx]; }
    }
    if (t == 1023) g_rowptr[N_NODES] = ssum[1023];
}
__global__ void k_scatter(const int* __restrict__ src, const int* __restrict__ dst) {
    int i = blockIdx.x * blockDim.x + threadIdx.x;
    if (i < E_EDGES) {
        int p = atomicAdd(&g_cursor[dst[i]], 1);
        g_esrc[p] = src[i];
    }
}

// ---------------- bf16 split helpers ----------------------------------------
__device__ __forceinline__ uint32_t pack_hi(float x, float y) {
    __nv_bfloat16 hx = __float2bfloat16(x), hy = __float2bfloat16(y);
    return ((uint32_t)__bfloat16_as_ushort(hy) << 16) | __bfloat16_as_ushort(hx);
}
__device__ __forceinline__ uint32_t pack_lo(float x, float y) {
    __nv_bfloat16 hx = __float2bfloat16(x), hy = __float2bfloat16(y);
    __nv_bfloat16 lx = __float2bfloat16(x - __bfloat162float(hx));
    __nv_bfloat16 ly = __float2bfloat16(y - __bfloat162float(hy));
    return ((uint32_t)__bfloat16_as_ushort(ly) << 16) | __bfloat16_as_ushort(lx);
}

__global__ void k_prepw(const float* __restrict__ wl, const float* __restrict__ wr,
                        uint32_t* __restrict__ hi, uint32_t* __restrict__ lo) {
    int i = blockIdx.x * blockDim.x + threadIdx.x;
    if (i >= 256 * 64) return;
    int n = i >> 6, p = i & 63;
    const float* wp = ((n < 128) ? wl : wr) + (size_t)(n & 127) * 128 + p * 2;
    float2 v = *(const float2*)wp;
    hi[i] = pack_hi(v.x, v.y);
    lo[i] = pack_lo(v.x, v.y);
}

// X fp32 -> bf16 hi/lo images (layer 1 only; layer 2 fused into k_node<1>)
__global__ void k_prepx(const float* __restrict__ X) {
    int i = blockIdx.x * blockDim.x + threadIdx.x;
    if (i >= N_NODES * 64) return;
    float2 v = *(const float2*)(X + (size_t)i * 2);
    g_xhi[i] = pack_hi(v.x, v.y);
    g_xlo[i] = pack_lo(v.x, v.y);
}

// ---------------- split-bf16 HMMA GEMM v4 ------------------------------------
// Tile M=128 x N=64, 256 threads (8 warps 4Mx2N), warp tile 32x32.
// All operands pre-converted bf16 images; prologue = pure cp.async (104 KB).
#define LDP   136
#define LDPU  68
#define SMEM_AHI 0
#define SMEM_ALO (SMEM_AHI + 128 * LDP * 2)      //  34816
#define SMEM_BHI (SMEM_ALO + 128 * LDP * 2)      //  69632
#define SMEM_BLO (SMEM_BHI + 64 * LDP * 2)       //  87040
#define SMEM_TOT (SMEM_BLO + 64 * LDP * 2)       // 104448

__device__ __forceinline__ void ldsm4(uint32_t& r0, uint32_t& r1, uint32_t& r2,
                                      uint32_t& r3, uint32_t addr) {
    asm volatile("ldmatrix.sync.aligned.m8n8.x4.shared.b16 {%0,%1,%2,%3}, [%4];"
                 : "=r"(r0), "=r"(r1), "=r"(r2), "=r"(r3) : "r"(addr));
}
__device__ __forceinline__ void mma16816(float* c, const uint32_t* a, const uint32_t* b) {
    asm volatile(
        "mma.sync.aligned.m16n8k16.row.col.f32.bf16.bf16.f32 "
        "{%0,%1,%2,%3}, {%4,%5,%6,%7}, {%8,%9}, {%0,%1,%2,%3};"
        : "+f"(c[0]), "+f"(c[1]), "+f"(c[2]), "+f"(c[3])
        : "r"(a[0]), "r"(a[1]), "r"(a[2]), "r"(a[3]), "r"(b[0]), "r"(b[1]));
}

__global__ void __launch_bounds__(256, 2)
k_gemm_tc(const uint32_t* __restrict__ whi, const uint32_t* __restrict__ wlo) {
    extern __shared__ char smem[];
    const uint32_t sb = s2u(smem);
    const int tid  = threadIdx.x;
    const int warp = tid >> 5;
    const int lane = tid & 31;
    const int mblk = blockIdx.x >> 2;
    const int nblk = blockIdx.x & 3;

    // ---- stage A (2x 32KB, predicated) + B (2x 16KB) via cp.async ----
    for (int c = tid; c < 2048; c += 256) {
        int row = c >> 4, seg = c & 15;
        long grow = (long)mblk * 128 + row;
        int sz = (grow < N_NODES) ? 16 : 0;
        uint32_t doff = (uint32_t)(row * (LDP * 2) + seg * 16);
        size_t soff = (size_t)grow * 256 + seg * 16;
        cpasync16p(sb + SMEM_AHI + doff, (const char*)g_xhi + soff, sz);
        cpasync16p(sb + SMEM_ALO + doff, (const char*)g_xlo + soff, sz);
    }
    {
        const char* bh = (const char*)(whi + (size_t)nblk * 64 * 64);
        const char* bl = (const char*)(wlo + (size_t)nblk * 64 * 64);
        for (int c = tid; c < 1024; c += 256) {
            int row = c >> 4, seg = c & 15;
            uint32_t doff = (uint32_t)(row * (LDP * 2) + seg * 16);
            uint32_t soff = (uint32_t)(row * 256 + seg * 16);
            cpasync16(sb + SMEM_BHI + doff, bh + soff);
            cpasync16(sb + SMEM_BLO + doff, bl + soff);
        }
    }
    asm volatile("cp.async.commit_group;" ::: "memory");
    asm volatile("cp.async.wait_group 0;" ::: "memory");
    __syncthreads();

    // ---- compute ----
    const int wm = (warp >> 1) * 32;
    const int wn = (warp & 1) * 32;
    float c[2][4][4];
#pragma unroll
    for (int mi = 0; mi < 2; mi++)
#pragma unroll
        for (int ni = 0; ni < 4; ni++)
#pragma unroll
            for (int q = 0; q < 4; q++) c[mi][ni][q] = 0.f;

    const uint32_t aRowOff = (uint32_t)((wm + (lane & 15)) * LDP + ((lane >> 4) << 3)) << 1;
    const uint32_t bRowOff = (uint32_t)((wn + ((lane >> 4) << 3) + (lane & 7)) * LDP
                                        + (((lane >> 3) & 1) << 3)) << 1;

#pragma unroll
    for (int term = 0; term < 3; term++) {
        const uint32_t Ab = sb + (term == 2 ? SMEM_ALO : SMEM_AHI) + aRowOff;
        const uint32_t Bb = sb + (term == 1 ? SMEM_BLO : SMEM_BHI) + bRowOff;
#pragma unroll
        for (int k0 = 0; k0 < 128; k0 += 16) {
            uint32_t a[2][4];
            ldsm4(a[0][0], a[0][1], a[0][2], a[0][3], Ab + (k0 << 1));
            ldsm4(a[1][0], a[1][1], a[1][2], a[1][3], Ab + ((16 * LDP) << 1) + (k0 << 1));
            uint32_t b[4][2];
#pragma unroll
            for (int nq = 0; nq < 2; nq++) {
                uint32_t r0, r1, r2, r3;
                ldsm4(r0, r1, r2, r3, Bb + ((nq * 16 * LDP) << 1) + (k0 << 1));
                b[nq * 2][0] = r0; b[nq * 2][1] = r1;
                b[nq * 2 + 1][0] = r2; b[nq * 2 + 1][1] = r3;
            }
#pragma unroll
            for (int mi = 0; mi < 2; mi++)
#pragma unroll
                for (int ni = 0; ni < 4; ni++)
                    mma16816(c[mi][ni], a[mi], b[ni]);
        }
    }

    // ---- epilogue ----
    float* buf = (nblk < 2) ? g_xl : g_xr;
    const int colbase = ((nblk * 64) & 127) + wn + (lane & 3) * 2;
#pragma unroll
    for (int mi = 0; mi < 2; mi++) {
#pragma unroll
        for (int half = 0; half < 2; half++) {
            long row = (long)mblk * 128 + wm + mi * 16 + (lane >> 2) + half * 8;
            if (row >= N_NODES) continue;
            float* rp = buf + row * HID + colbase;
#pragma unroll
            for (int ni = 0; ni < 4; ni++) {
                float2 v = make_float2(c[mi][ni][half * 2], c[mi][ni][half * 2 + 1]);
                *(float2*)(rp + ni * 8) = v;
            }
        }
    }
}

// ---------------- fused per-node attention ---------------------------------
// LAYER==1 additionally writes h1 bf16 hi/lo images for the layer-2 GEMM.
template <int LAYER>
__global__ void k_node(const float* __restrict__ att, const float* __restrict__ b,
                       float* __restrict__ outbuf) {
    const int n    = (blockIdx.x * blockDim.x + threadIdx.x) >> 5;
    const int lane = threadIdx.x & 31;
    if (n >= N_NODES) return;

    const int beg = g_rowptr[n];
    const int end = g_rowptr[n + 1];

    const float4 xr = *(const float4*)(g_xr + (size_t)n * HID + lane * 4);
    const float4 at = *(const float4*)(att + lane * 4);

    float4 acc = make_float4(0.f, 0.f, 0.f, 0.f);
    float  sum = 0.f;

    for (int i0 = beg; i0 < end; i0 += 32) {
        const int cnt = min(32, end - i0);
        int sid = (lane < cnt) ? g_esrc[i0 + lane] : 0;
        for (int j = 0; j < cnt; j++) {
            const int s = __shfl_sync(0xffffffffu, sid, j);
            const float4 xl = *(const float4*)(g_xl + (size_t)s * HID + lane * 4);
            float p = lrelu(xl.x + xr.x, ATT_SLOPE) * at.x
                    + lrelu(xl.y + xr.y, ATT_SLOPE) * at.y
                    + lrelu(xl.z + xr.z, ATT_SLOPE) * at.z
                    + lrelu(xl.w + xr.w, ATT_SLOPE) * at.w;
            p += __shfl_xor_sync(0xffffffffu, p, 8);
            p += __shfl_xor_sync(0xffffffffu, p, 4);
            p += __shfl_xor_sync(0xffffffffu, p, 2);
            p += __shfl_xor_sync(0xffffffffu, p, 1);
            const float ex = __expf(p);
            sum += ex;
            acc.x = fmaf(ex, xl.x, acc.x);
            acc.y = fmaf(ex, xl.y, acc.y);
            acc.z = fmaf(ex, xl.z, acc.z);
            acc.w = fmaf(ex, xl.w, acc.w);
        }
    }

    const float inv = 1.f / (sum + 1e-16f);
    const float4 bb = *(const float4*)(b + lane * 4);
    float4 o;
    o.x = fmaf(acc.x, inv, bb.x);
    o.y = fmaf(acc.y, inv, bb.y);
    o.z = fmaf(acc.z, inv, bb.z);
    o.w = fmaf(acc.w, inv, bb.w);

    float* dstp = outbuf + (size_t)n * HID + lane * 4;
    if (LAYER == 1) {
        o.x = lrelu(o.x, OUT_SLOPE);
        o.y = lrelu(o.y, OUT_SLOPE);
        o.z = lrelu(o.z, OUT_SLOPE);
        o.w = lrelu(o.w, OUT_SLOPE);
        *(float4*)dstp = o;
        // bf16 hi/lo image of h1 for the layer-2 GEMM
        const size_t ib = (size_t)n * 64 + lane * 2;
        uint2 hi = make_uint2(pack_hi(o.x, o.y), pack_hi(o.z, o.w));
        uint2 lo = make_uint2(pack_lo(o.x, o.y), pack_lo(o.z, o.w));
        *(uint2*)(g_xhi + ib) = hi;
        *(uint2*)(g_xlo + ib) = lo;
    } else {
        const float4 h = *(const float4*)(g_h1 + (size_t)n * HID + lane * 4);
        o.x += h.x; o.y += h.y; o.z += h.z; o.w += h.w;
        *(float4*)dstp = o;
    }
}

// ---------------- launch ----------------
extern "C" void kernel_launch(void* const* d_in, const int* in_sizes, int n_in,
                              void* d_out, int out_size) {
    const float* x    = (const float*)d_in[0];
    const int*   ei   = (const int*)d_in[1];
    const float* wl1  = (const float*)d_in[2];
    const float* wr1  = (const float*)d_in[3];
    const float* att1 = (const float*)d_in[4];
    const float* b1   = (const float*)d_in[5];
    const float* wl2  = (const float*)d_in[6];
    const float* wr2  = (const float*)d_in[7];
    const float* att2 = (const float*)d_in[8];
    const float* b2   = (const float*)d_in[9];
    float* out = (float*)d_out;

    const int* src = ei;
    const int* dst = ei + E_EDGES;

    void* h1_ptr = nullptr;
    cudaGetSymbolAddress(&h1_ptr, g_h1);
    void *w1hi, *w1lo, *w2hi, *w2lo;
    cudaGetSymbolAddress(&w1hi, g_w1hi);
    cudaGetSymbolAddress(&w1lo, g_w1lo);
    cudaGetSymbolAddress(&w2hi, g_w2hi);
    cudaGetSymbolAddress(&w2lo, g_w2lo);

    // side stream + events, created once on the first (non-captured) call
    static cudaStream_t s1 = nullptr;
    static cudaEvent_t ev_fork = nullptr, ev_join = nullptr;
    if (s1 == nullptr) {
        cudaStreamCreateWithFlags(&s1, cudaStreamNonBlocking);
        cudaEventCreateWithFlags(&ev_fork, cudaEventDisableTiming);
        cudaEventCreateWithFlags(&ev_join, cudaEventDisableTiming);
    }

    cudaFuncSetAttribute(k_gemm_tc, cudaFuncAttributeMaxDynamicSharedMemorySize, SMEM_TOT);

    const int gemm_blocks = ((N_NODES + 127) / 128) * 4;    // 1564
    const int node_blocks = (N_NODES * 32 + 255) / 256;     // 6250
    const int e_blocks    = (E_EDGES + 255) / 256;
    const int n_blocks    = (N_NODES + 255) / 256;
    const int w_blocks    = (256 * 64 + 255) / 256;         // 64
    const int px_blocks   = (N_NODES * 64 + 255) / 256;     // 12500

    // s0 (capture stream): prepw1, prepx, gemm1(slot 4), node1, gemm2, node2
    // s1 (forked):         prepw2, CSR build  — joins before node1
    k_prepw<<<w_blocks, 256>>>(wl1, wr1, (uint32_t*)w1hi, (uint32_t*)w1lo);
    k_prepx<<<px_blocks, 256>>>(x);

    cudaEventRecord(ev_fork, 0);
    cudaStreamWaitEvent(s1, ev_fork, 0);
    k_prepw<<<w_blocks, 256, 0, s1>>>(wl2, wr2, (uint32_t*)w2hi, (uint32_t*)w2lo);

    k_gemm_tc<<<gemm_blocks, 256, SMEM_TOT>>>((const uint32_t*)w1hi, (const uint32_t*)w1lo);

    k_zero_deg<<<n_blocks, 256, 0, s1>>>();
    k_hist<<<e_blocks, 256, 0, s1>>>(dst);
    k_scan<<<1, 1024, 0, s1>>>();
    k_scatter<<<e_blocks, 256, 0, s1>>>(src, dst);
    cudaEventRecord(ev_join, s1);
    cudaStreamWaitEvent(0, ev_join, 0);

    k_node<1><<<node_blocks, 256>>>(att1, b1, (float*)h1_ptr);
    k_gemm_tc<<<gemm_blocks, 256, SMEM_TOT>>>((const uint32_t*)w2hi, (const uint32_t*)w2lo);
    k_node<2><<<node_blocks, 256>>>(att2, b2, out);
}